// round 15
// baseline (speedup 1.0000x reference)
#include <cuda_runtime.h>
#include <cuda_fp16.h>

#define N_NODES    262144
#define N_EDGES    4194304
#define NUM_GRAPHS 1024

typedef unsigned long long u64;

// ---------------- scratch (device globals; no allocations allowed) ----------
struct __align__(16) NodeRec16 {
    __half2 xa;   // x0, x1
    __half2 xb;   // x2, x3
    __half2 pa;   // px, py
    __half2 pb;   // pz, 0
};
__device__ NodeRec16 g_rec[N_NODES];          // 16B per node -> 1 LDG.128 gather
__device__ uint4     g_aggh[N_NODES * 2];     // Σ silu(hid) in fp16: 16 halves per node
__device__ float     g_cnt[N_NODES];          // edge counts
__device__ float4    g_pooled[NUM_GRAPHS * 8];// pooled: (NUM_GRAPHS, 2, 16)

// ---------------- packed f32x2 helpers (Blackwell FFMA2 path) ----------------
__device__ __forceinline__ u64 pack2(float lo, float hi) {
    u64 r; asm("mov.b64 %0, {%1,%2};" : "=l"(r) : "f"(lo), "f"(hi)); return r;
}
__device__ __forceinline__ void unpack2(u64 v, float& lo, float& hi) {
    asm("mov.b64 {%0,%1}, %2;" : "=f"(lo), "=f"(hi) : "l"(v));
}
__device__ __forceinline__ u64 fma2(u64 a, u64 b, u64 c) {
    u64 d; asm("fma.rn.f32x2 %0, %1, %2, %3;" : "=l"(d) : "l"(a), "l"(b), "l"(c)); return d;
}

// pack two f32 into f16x2 (lo in low half, hi in high half)
__device__ __forceinline__ unsigned pack_h2(float lo, float hi) {
    unsigned d; asm("cvt.rn.f16x2.f32 %0, %1, %2;" : "=r"(d) : "f"(hi), "f"(lo)); return d;
}

// SiLU via single-MUFU tanh: silu(u) = 0.5u * (1 + tanh(u/2))
__device__ __forceinline__ float silu_f(float u) {
    float hu = 0.5f * u;
    float th; asm("tanh.approx.f32 %0, %1;" : "=f"(th) : "f"(hu));
    return fmaf(hu, th, hu);
}

// ---------------- reduction helpers ----------------
__device__ __forceinline__ void red_add_v4h2(uint4* addr, unsigned a, unsigned b,
                                             unsigned c, unsigned d) {
    asm volatile("red.global.add.noftz.v4.f16x2 [%0], {%1,%2,%3,%4};"
                 :: "l"(addr), "r"(a), "r"(b), "r"(c), "r"(d) : "memory");
}
__device__ __forceinline__ void red_add_v4(float4* addr, float a, float b, float c, float d) {
    asm volatile("red.global.add.v4.f32 [%0], {%1,%2,%3,%4};"
                 :: "l"(addr), "f"(a), "f"(b), "f"(c), "f"(d) : "memory");
}
__device__ __forceinline__ void red_add_f(float* addr, float v) {
    asm volatile("red.global.add.f32 [%0], %1;" :: "l"(addr), "f"(v) : "memory");
}

// ---------------- kernel 0: build fp16 record + zero agg/cnt/pooled ----------
__global__ void __launch_bounds__(256) pre_kernel(
    const float* __restrict__ x, const float* __restrict__ pos)
{
    int n = blockIdx.x * 256 + threadIdx.x;
    if (n >= N_NODES) return;
    float4 xv = reinterpret_cast<const float4*>(x)[n];
    NodeRec16 r;
    r.xa = __floats2half2_rn(xv.x, xv.y);
    r.xb = __floats2half2_rn(xv.z, xv.w);
    r.pa = __floats2half2_rn(pos[3 * n + 0], pos[3 * n + 1]);
    r.pb = __floats2half2_rn(pos[3 * n + 2], 0.f);
    g_rec[n] = r;

    g_aggh[2 * n + 0] = make_uint4(0u, 0u, 0u, 0u);
    g_aggh[2 * n + 1] = make_uint4(0u, 0u, 0u, 0u);
    g_cnt[n] = 0.f;
    if (n < NUM_GRAPHS * 8) g_pooled[n] = make_float4(0.f, 0.f, 0.f, 0.f);
}

// ---------------- kernel 1: edge layer1+SiLU + fp16 scatter ------------------
__global__ void __launch_bounds__(256) edge_kernel(
    const int* __restrict__ ei,
    const float* __restrict__ w1, const float* __restrict__ b1)
{
    __shared__ u64 sw1p[72];   // 9 rows x 8 channel-pairs
    __shared__ u64 sb1p[8];

    int t = threadIdx.x;
    if (t < 72)                sw1p[t]      = pack2(w1[2 * t],        w1[2 * t + 1]);
    else if (t < 80)           sb1p[t - 72] = pack2(b1[2 * (t - 72)], b1[2 * (t - 72) + 1]);
    __syncthreads();

    int e = blockIdx.x * 256 + t;
    if (e >= N_EDGES) return;

    int s = ei[e];
    int d = ei[N_EDGES + e];

    // one 16B load per node
    NodeRec16 rs = g_rec[s];
    NodeRec16 rd = g_rec[d];

    float2 xs01 = __half22float2(rs.xa);
    float2 xs23 = __half22float2(rs.xb);
    float2 ps01 = __half22float2(rs.pa);
    float  psz  = __half2float(__low2half(rs.pb));
    float2 xd01 = __half22float2(rd.xa);
    float2 xd23 = __half22float2(rd.xb);
    float2 pd01 = __half22float2(rd.pa);
    float  pdz  = __half2float(__low2half(rd.pb));

    float rx = ps01.x - pd01.x;
    float ry = ps01.y - pd01.y;
    float rz = psz    - pdz;
    float dist = sqrtf(fmaf(rx, rx, fmaf(ry, ry, rz * rz)));

    float feat[9];
    feat[0] = xd01.x; feat[1] = xd01.y; feat[2] = xd23.x; feat[3] = xd23.y;
    feat[4] = xs01.x; feat[5] = xs01.y; feat[6] = xs23.x; feat[7] = xs23.y;
    feat[8] = dist;

    // layer 1: 72 FFMA2
    u64 acc[8];
#pragma unroll
    for (int j = 0; j < 8; j++) acc[j] = sb1p[j];
#pragma unroll
    for (int i = 0; i < 9; i++) {
        u64 ff = pack2(feat[i], feat[i]);
#pragma unroll
        for (int j = 0; j < 8; j++) acc[j] = fma2(ff, sw1p[i * 8 + j], acc[j]);
    }

    // SiLU + pack to f16x2
    unsigned hp[8];
#pragma unroll
    for (int k = 0; k < 8; k++) {
        float a, b;
        unpack2(acc[k], a, b);
        hp[k] = pack_h2(silu_f(a), silu_f(b));
    }

    uint4* aggp = &g_aggh[d * 2];
    red_add_v4h2(aggp + 0, hp[0], hp[1], hp[2], hp[3]);
    red_add_v4h2(aggp + 1, hp[4], hp[5], hp[6], hp[7]);
    red_add_f(&g_cnt[d], 1.0f);
}

// ---------------- kernel 2: node W2 + mean/relu + softmax + pooling ----------
__global__ void __launch_bounds__(256) node_kernel(
    const int* __restrict__ batch,
    const float* __restrict__ w2, const float* __restrict__ b2,
    const float* __restrict__ pool_w, const float* __restrict__ pool_b,
    float* __restrict__ out_s)
{
    __shared__ u64 sw2p[128];   // 16 rows x 8 channel-pairs (row-major w2)
    __shared__ u64 sb2p[8];

    int t = threadIdx.x;
    if (t < 128)               sw2p[t]       = pack2(w2[2 * t],         w2[2 * t + 1]);
    else if (t < 136)          sb2p[t - 128] = pack2(b2[2 * (t - 128)], b2[2 * (t - 128) + 1]);
    __syncthreads();

    int n = blockIdx.x * blockDim.x + t;
    if (n >= N_NODES) return;

    uint4 q0 = g_aggh[2 * n + 0];
    uint4 q1 = g_aggh[2 * n + 1];
    float S[16];
    {
        float2 p;
        p = __half22float2(*reinterpret_cast<__half2*>(&q0.x)); S[0]=p.x;  S[1]=p.y;
        p = __half22float2(*reinterpret_cast<__half2*>(&q0.y)); S[2]=p.x;  S[3]=p.y;
        p = __half22float2(*reinterpret_cast<__half2*>(&q0.z)); S[4]=p.x;  S[5]=p.y;
        p = __half22float2(*reinterpret_cast<__half2*>(&q0.w)); S[6]=p.x;  S[7]=p.y;
        p = __half22float2(*reinterpret_cast<__half2*>(&q1.x)); S[8]=p.x;  S[9]=p.y;
        p = __half22float2(*reinterpret_cast<__half2*>(&q1.y)); S[10]=p.x; S[11]=p.y;
        p = __half22float2(*reinterpret_cast<__half2*>(&q1.z)); S[12]=p.x; S[13]=p.y;
        p = __half22float2(*reinterpret_cast<__half2*>(&q1.w)); S[14]=p.x; S[15]=p.y;
    }

    float fc  = g_cnt[n];
    float inv = __frcp_rn(fmaxf(fc, 1.0f));

    // num = S @ W2 + fc * b2  (exact redistribution of per-edge W2)
    u64 facc[8];
    u64 fcp = pack2(fc, fc);
#pragma unroll
    for (int j = 0; j < 8; j++) {
        u64 zz = pack2(0.f, 0.f);
        facc[j] = fma2(fcp, sb2p[j], zz);
    }
#pragma unroll
    for (int i = 0; i < 16; i++) {
        u64 ss = pack2(S[i], S[i]);
#pragma unroll
        for (int j = 0; j < 8; j++) facc[j] = fma2(ss, sw2p[i * 8 + j], facc[j]);
    }

    float h[16];
#pragma unroll
    for (int j = 0; j < 8; j++) {
        float a, b;
        unpack2(facc[j], a, b);
        h[2 * j + 0] = fmaxf(a * inv, 0.f);
        h[2 * j + 1] = fmaxf(b * inv, 0.f);
    }

    float l0 = pool_b[0], l1 = pool_b[1];
#pragma unroll
    for (int i = 0; i < 16; i++) {
        l0 = fmaf(h[i], pool_w[i * 2 + 0], l0);
        l1 = fmaf(h[i], pool_w[i * 2 + 1], l1);
    }
    float mm = fmaxf(l0, l1);
    float e0 = __expf(l0 - mm), e1 = __expf(l1 - mm);
    float is = __frcp_rn(e0 + e1);
    float s0 = e0 * is, s1 = e1 * is;

    reinterpret_cast<float2*>(out_s)[n] = make_float2(s0, s1);

    int g = batch[n];
    const unsigned full = 0xffffffffu;
    int g0 = __shfl_sync(full, g, 0);
    bool uni = __all_sync(full, g == g0);

    float v[32];
#pragma unroll
    for (int i = 0; i < 16; i++) { v[i] = s0 * h[i]; v[16 + i] = s1 * h[i]; }

    if (uni) {
#pragma unroll
        for (int j = 0; j < 32; j++) {
            float sv = v[j];
            sv += __shfl_xor_sync(full, sv, 16);
            sv += __shfl_xor_sync(full, sv, 8);
            sv += __shfl_xor_sync(full, sv, 4);
            sv += __shfl_xor_sync(full, sv, 2);
            sv += __shfl_xor_sync(full, sv, 1);
            v[j] = sv;
        }
        int lane = t & 31;
        float4* pp = &g_pooled[g0 * 8];
        switch (lane) {
            case 0: red_add_v4(pp + 0, v[0],  v[1],  v[2],  v[3]);  break;
            case 1: red_add_v4(pp + 1, v[4],  v[5],  v[6],  v[7]);  break;
            case 2: red_add_v4(pp + 2, v[8],  v[9],  v[10], v[11]); break;
            case 3: red_add_v4(pp + 3, v[12], v[13], v[14], v[15]); break;
            case 4: red_add_v4(pp + 4, v[16], v[17], v[18], v[19]); break;
            case 5: red_add_v4(pp + 5, v[20], v[21], v[22], v[23]); break;
            case 6: red_add_v4(pp + 6, v[24], v[25], v[26], v[27]); break;
            case 7: red_add_v4(pp + 7, v[28], v[29], v[30], v[31]); break;
            default: break;
        }
    } else {
        float4* pp = &g_pooled[g * 8];
        red_add_v4(pp + 0, v[0],  v[1],  v[2],  v[3]);
        red_add_v4(pp + 1, v[4],  v[5],  v[6],  v[7]);
        red_add_v4(pp + 2, v[8],  v[9],  v[10], v[11]);
        red_add_v4(pp + 3, v[12], v[13], v[14], v[15]);
        red_add_v4(pp + 4, v[16], v[17], v[18], v[19]);
        red_add_v4(pp + 5, v[20], v[21], v[22], v[23]);
        red_add_v4(pp + 6, v[24], v[25], v[26], v[27]);
        red_add_v4(pp + 7, v[28], v[29], v[30], v[31]);
    }
}

// ---------------- kernel 3: per-graph head (one warp per graph) -------------
__global__ void __launch_bounds__(32) graph_kernel(
    const float* __restrict__ toz_w, const float* __restrict__ toz_b,
    const float* __restrict__ vp_w1, const float* __restrict__ vp_b1,
    const float* __restrict__ vp_w2, const float* __restrict__ vp_b2,
    const float* __restrict__ bridge_w, const float* __restrict__ bridge_b,
    float* __restrict__ out_recon,   // (1024, 8, 4)
    float* __restrict__ out_z,       // (1024, 2, 4)
    float* __restrict__ out_forces,  // (1024, 2, 2)
    float* __restrict__ out_V)       // (1024, 1)
{
    const unsigned full = 0xffffffffu;
    int g = blockIdx.x;
    int l = threadIdx.x;
    int k = l >> 4;
    int idx = l & 15;

    float p = reinterpret_cast<const float*>(&g_pooled[g * 8])[l];

    float z[8];
#pragma unroll
    for (int c = 0; c < 4; c++) {
        float prod = p * toz_w[idx * 4 + c];
        prod += __shfl_xor_sync(full, prod, 8);
        prod += __shfl_xor_sync(full, prod, 4);
        prod += __shfl_xor_sync(full, prod, 2);
        prod += __shfl_xor_sync(full, prod, 1);
        float zo = prod + toz_b[c];
        float zx = __shfl_xor_sync(full, zo, 16);
        z[k * 4 + c] = zo;
        z[(1 - k) * 4 + c] = zx;
    }

    if (l < 8) out_z[g * 8 + l] = z[l];

    {
        float acc = bridge_b[l];
#pragma unroll
        for (int i = 0; i < 8; i++)
            acc = fmaf(z[i], bridge_w[i * 32 + l], acc);
        out_recon[g * 32 + l] = acc;
    }

    float dx = z[0] - z[4];
    float dy = z[1] - z[5];
    float dist = sqrtf(dx * dx + dy * dy + 1e-6f);

    float w1 = vp_w1[l];
    float w2 = vp_w2[l];
    float tt = fmaf(dist, w1, vp_b1[l]);
    float u  = __expf(-fabsf(tt));
    float sp = fmaxf(tt, 0.f) + __logf(1.f + u);
    float Vp = sp * w2;
    float sig = __frcp_rn(1.f + __expf(-tt));
    float fpp = sig * w1 * w2;

#pragma unroll
    for (int off = 16; off >= 1; off >>= 1) {
        Vp  += __shfl_xor_sync(full, Vp,  off);
        fpp += __shfl_xor_sync(full, fpp, off);
    }

    if (l == 0) {
        float c = fpp / dist;
        out_forces[g * 4 + 0] = -c * dx;
        out_forces[g * 4 + 1] = -c * dy;
        out_forces[g * 4 + 2] =  c * dx;
        out_forces[g * 4 + 3] =  c * dy;
        out_V[g] = Vp + vp_b2[0];
    }
}

// ---------------- launch -----------------------------------------------------
extern "C" void kernel_launch(void* const* d_in, const int* in_sizes, int n_in,
                              void* d_out, int out_size)
{
    const float* x        = (const float*)d_in[0];
    const float* pos      = (const float*)d_in[1];
    const int*   ei       = (const int*)  d_in[2];
    const int*   batch    = (const int*)  d_in[3];
    const float* enc_w1   = (const float*)d_in[4];
    const float* enc_b1   = (const float*)d_in[5];
    const float* enc_w2   = (const float*)d_in[6];
    const float* enc_b2   = (const float*)d_in[7];
    const float* pool_w   = (const float*)d_in[8];
    const float* pool_b   = (const float*)d_in[9];
    const float* toz_w    = (const float*)d_in[10];
    const float* toz_b    = (const float*)d_in[11];
    const float* vp_w1    = (const float*)d_in[12];
    const float* vp_b1    = (const float*)d_in[13];
    const float* vp_w2    = (const float*)d_in[14];
    const float* vp_b2    = (const float*)d_in[15];
    const float* bridge_w = (const float*)d_in[16];
    const float* bridge_b = (const float*)d_in[17];

    float* out = (float*)d_out;
    float* out_recon  = out;                 // 1024*8*4 = 32768
    float* out_z      = out + 32768;         // 1024*2*4 =  8192
    float* out_s      = out + 40960;         // 262144*2 = 524288
    float* out_forces = out + 565248;        // 1024*2*2 =  4096
    float* out_V      = out + 569344;        // 1024

    pre_kernel<<<N_NODES / 256, 256>>>(x, pos);

    edge_kernel<<<N_EDGES / 256, 256>>>(ei, enc_w1, enc_b1);

    node_kernel<<<N_NODES / 256, 256>>>(batch, enc_w2, enc_b2, pool_w, pool_b, out_s);

    graph_kernel<<<NUM_GRAPHS, 32>>>(toz_w, toz_b, vp_w1, vp_b1, vp_w2, vp_b2,
                                     bridge_w, bridge_b,
                                     out_recon, out_z, out_forces, out_V);
}

// round 16
// speedup vs baseline: 1.2712x; 1.2712x over previous
#include <cuda_runtime.h>
#include <cuda_fp16.h>

#define N_NODES    262144
#define N_EDGES    4194304
#define NUM_GRAPHS 1024

typedef unsigned long long u64;

// ---------------- scratch (device globals; no allocations allowed) ----------
struct __align__(16) NodeRec16 {
    __half2 xa;   // x0, x1
    __half2 xb;   // x2, x3
    __half2 pa;   // px, py
    __half2 pb;   // pz, 0
};
__device__ NodeRec16 g_rec[N_NODES];          // 16B per node -> 1 LDG.128 gather
__device__ float4    g_agg[N_NODES * 4];      // Σ silu(hid): (N_NODES, 16) f32
__device__ float     g_cnt[N_NODES];          // edge counts
__device__ float4    g_pooled[NUM_GRAPHS * 8];// pooled: (NUM_GRAPHS, 2, 16)

// ---------------- packed f32x2 helpers (Blackwell FFMA2 path) ----------------
__device__ __forceinline__ u64 pack2(float lo, float hi) {
    u64 r; asm("mov.b64 %0, {%1,%2};" : "=l"(r) : "f"(lo), "f"(hi)); return r;
}
__device__ __forceinline__ void unpack2(u64 v, float& lo, float& hi) {
    asm("mov.b64 {%0,%1}, %2;" : "=f"(lo), "=f"(hi) : "l"(v));
}
__device__ __forceinline__ u64 fma2(u64 a, u64 b, u64 c) {
    u64 d; asm("fma.rn.f32x2 %0, %1, %2, %3;" : "=l"(d) : "l"(a), "l"(b), "l"(c)); return d;
}

// SiLU via single-MUFU tanh: silu(u) = 0.5u * (1 + tanh(u/2))
__device__ __forceinline__ float silu_f(float u) {
    float hu = 0.5f * u;
    float th; asm("tanh.approx.f32 %0, %1;" : "=f"(th) : "f"(hu));
    return fmaf(hu, th, hu);
}

// ---------------- reduction helpers (fp32 red.v4 — the fast LTS path) --------
__device__ __forceinline__ void red_add_v4(float4* addr, float a, float b, float c, float d) {
    asm volatile("red.global.add.v4.f32 [%0], {%1,%2,%3,%4};"
                 :: "l"(addr), "f"(a), "f"(b), "f"(c), "f"(d) : "memory");
}
__device__ __forceinline__ void red_add_f(float* addr, float v) {
    asm volatile("red.global.add.f32 [%0], %1;" :: "l"(addr), "f"(v) : "memory");
}

// ---------------- kernel 0: build fp16 record + zero agg/cnt/pooled ----------
__global__ void __launch_bounds__(256) pre_kernel(
    const float* __restrict__ x, const float* __restrict__ pos)
{
    int n = blockIdx.x * 256 + threadIdx.x;
    if (n >= N_NODES) return;
    float4 xv = reinterpret_cast<const float4*>(x)[n];
    NodeRec16 r;
    r.xa = __floats2half2_rn(xv.x, xv.y);
    r.xb = __floats2half2_rn(xv.z, xv.w);
    r.pa = __floats2half2_rn(pos[3 * n + 0], pos[3 * n + 1]);
    r.pb = __floats2half2_rn(pos[3 * n + 2], 0.f);
    g_rec[n] = r;

    const float4 z = make_float4(0.f, 0.f, 0.f, 0.f);
#pragma unroll
    for (int k = 0; k < 4; k++) g_agg[n * 4 + k] = z;
    g_cnt[n] = 0.f;
    if (n < NUM_GRAPHS * 8) g_pooled[n] = z;
}

// ---------------- kernel 1: edge layer1+SiLU + fp32 scatter (4 edges/thread) -
__global__ void __launch_bounds__(256) edge_kernel(
    const int* __restrict__ ei,
    const float* __restrict__ w1, const float* __restrict__ b1)
{
    __shared__ u64 sw1p[72];   // 9 rows x 8 channel-pairs
    __shared__ u64 sb1p[8];

    int t = threadIdx.x;
    if (t < 72)                sw1p[t]      = pack2(w1[2 * t],        w1[2 * t + 1]);
    else if (t < 80)           sb1p[t - 72] = pack2(b1[2 * (t - 72)], b1[2 * (t - 72) + 1]);
    __syncthreads();

    int q = blockIdx.x * 256 + t;            // quad index (4 edges per thread)
    int4 s4 = reinterpret_cast<const int4*>(ei)[q];
    int4 d4 = reinterpret_cast<const int4*>(ei + N_EDGES)[q];

    // front-batch all 8 record gathers (MLP=8) so L2 latency overlaps
    NodeRec16 rs0 = g_rec[s4.x], rd0 = g_rec[d4.x];
    NodeRec16 rs1 = g_rec[s4.y], rd1 = g_rec[d4.y];
    NodeRec16 rs2 = g_rec[s4.z], rd2 = g_rec[d4.z];
    NodeRec16 rs3 = g_rec[s4.w], rd3 = g_rec[d4.w];

#pragma unroll
    for (int eidx = 0; eidx < 4; eidx++) {
        NodeRec16 rs = (eidx == 0) ? rs0 : (eidx == 1) ? rs1 : (eidx == 2) ? rs2 : rs3;
        NodeRec16 rd = (eidx == 0) ? rd0 : (eidx == 1) ? rd1 : (eidx == 2) ? rd2 : rd3;
        int d      = (eidx == 0) ? d4.x : (eidx == 1) ? d4.y : (eidx == 2) ? d4.z : d4.w;

        float2 xs01 = __half22float2(rs.xa);
        float2 xs23 = __half22float2(rs.xb);
        float2 ps01 = __half22float2(rs.pa);
        float  psz  = __half2float(__low2half(rs.pb));
        float2 xd01 = __half22float2(rd.xa);
        float2 xd23 = __half22float2(rd.xb);
        float2 pd01 = __half22float2(rd.pa);
        float  pdz  = __half2float(__low2half(rd.pb));

        float rx = ps01.x - pd01.x;
        float ry = ps01.y - pd01.y;
        float rz = psz    - pdz;
        float dist = sqrtf(fmaf(rx, rx, fmaf(ry, ry, rz * rz)));

        float feat[9];
        feat[0] = xd01.x; feat[1] = xd01.y; feat[2] = xd23.x; feat[3] = xd23.y;
        feat[4] = xs01.x; feat[5] = xs01.y; feat[6] = xs23.x; feat[7] = xs23.y;
        feat[8] = dist;

        // layer 1: 72 FFMA2
        u64 acc[8];
#pragma unroll
        for (int j = 0; j < 8; j++) acc[j] = sb1p[j];
#pragma unroll
        for (int i = 0; i < 9; i++) {
            u64 ff = pack2(feat[i], feat[i]);
#pragma unroll
            for (int j = 0; j < 8; j++) acc[j] = fma2(ff, sw1p[i * 8 + j], acc[j]);
        }

        // SiLU (single MUFU each)
        float h[16];
#pragma unroll
        for (int k = 0; k < 8; k++) {
            float a, b;
            unpack2(acc[k], a, b);
            h[2 * k + 0] = silu_f(a);
            h[2 * k + 1] = silu_f(b);
        }

        float4* aggp = &g_agg[d * 4];
        red_add_v4(aggp + 0, h[0],  h[1],  h[2],  h[3]);
        red_add_v4(aggp + 1, h[4],  h[5],  h[6],  h[7]);
        red_add_v4(aggp + 2, h[8],  h[9],  h[10], h[11]);
        red_add_v4(aggp + 3, h[12], h[13], h[14], h[15]);
        red_add_f(&g_cnt[d], 1.0f);
    }
}

// ---------------- kernel 2: node W2 + mean/relu + softmax + pooling ----------
__global__ void __launch_bounds__(256) node_kernel(
    const int* __restrict__ batch,
    const float* __restrict__ w2, const float* __restrict__ b2,
    const float* __restrict__ pool_w, const float* __restrict__ pool_b,
    float* __restrict__ out_s)
{
    __shared__ u64 sw2p[128];   // 16 rows x 8 channel-pairs (row-major w2)
    __shared__ u64 sb2p[8];

    int t = threadIdx.x;
    if (t < 128)               sw2p[t]       = pack2(w2[2 * t],         w2[2 * t + 1]);
    else if (t < 136)          sb2p[t - 128] = pack2(b2[2 * (t - 128)], b2[2 * (t - 128) + 1]);
    __syncthreads();

    int n = blockIdx.x * blockDim.x + t;
    if (n >= N_NODES) return;

    float4 a0 = g_agg[n * 4 + 0];
    float4 a1 = g_agg[n * 4 + 1];
    float4 a2 = g_agg[n * 4 + 2];
    float4 a3 = g_agg[n * 4 + 3];
    float S[16] = {a0.x, a0.y, a0.z, a0.w, a1.x, a1.y, a1.z, a1.w,
                   a2.x, a2.y, a2.z, a2.w, a3.x, a3.y, a3.z, a3.w};

    float fc  = g_cnt[n];
    float inv = __frcp_rn(fmaxf(fc, 1.0f));

    // num = S @ W2 + fc * b2  (exact redistribution of per-edge W2)
    u64 facc[8];
    u64 fcp = pack2(fc, fc);
#pragma unroll
    for (int j = 0; j < 8; j++) {
        u64 zz = pack2(0.f, 0.f);
        facc[j] = fma2(fcp, sb2p[j], zz);
    }
#pragma unroll
    for (int i = 0; i < 16; i++) {
        u64 ss = pack2(S[i], S[i]);
#pragma unroll
        for (int j = 0; j < 8; j++) facc[j] = fma2(ss, sw2p[i * 8 + j], facc[j]);
    }

    float h[16];
#pragma unroll
    for (int j = 0; j < 8; j++) {
        float a, b;
        unpack2(facc[j], a, b);
        h[2 * j + 0] = fmaxf(a * inv, 0.f);
        h[2 * j + 1] = fmaxf(b * inv, 0.f);
    }

    float l0 = pool_b[0], l1 = pool_b[1];
#pragma unroll
    for (int i = 0; i < 16; i++) {
        l0 = fmaf(h[i], pool_w[i * 2 + 0], l0);
        l1 = fmaf(h[i], pool_w[i * 2 + 1], l1);
    }
    float mm = fmaxf(l0, l1);
    float e0 = __expf(l0 - mm), e1 = __expf(l1 - mm);
    float is = __frcp_rn(e0 + e1);
    float s0 = e0 * is, s1 = e1 * is;

    reinterpret_cast<float2*>(out_s)[n] = make_float2(s0, s1);

    int g = batch[n];
    const unsigned full = 0xffffffffu;
    int g0 = __shfl_sync(full, g, 0);
    bool uni = __all_sync(full, g == g0);

    float v[32];
#pragma unroll
    for (int i = 0; i < 16; i++) { v[i] = s0 * h[i]; v[16 + i] = s1 * h[i]; }

    if (uni) {
#pragma unroll
        for (int j = 0; j < 32; j++) {
            float sv = v[j];
            sv += __shfl_xor_sync(full, sv, 16);
            sv += __shfl_xor_sync(full, sv, 8);
            sv += __shfl_xor_sync(full, sv, 4);
            sv += __shfl_xor_sync(full, sv, 2);
            sv += __shfl_xor_sync(full, sv, 1);
            v[j] = sv;
        }
        int lane = t & 31;
        float4* pp = &g_pooled[g0 * 8];
        switch (lane) {
            case 0: red_add_v4(pp + 0, v[0],  v[1],  v[2],  v[3]);  break;
            case 1: red_add_v4(pp + 1, v[4],  v[5],  v[6],  v[7]);  break;
            case 2: red_add_v4(pp + 2, v[8],  v[9],  v[10], v[11]); break;
            case 3: red_add_v4(pp + 3, v[12], v[13], v[14], v[15]); break;
            case 4: red_add_v4(pp + 4, v[16], v[17], v[18], v[19]); break;
            case 5: red_add_v4(pp + 5, v[20], v[21], v[22], v[23]); break;
            case 6: red_add_v4(pp + 6, v[24], v[25], v[26], v[27]); break;
            case 7: red_add_v4(pp + 7, v[28], v[29], v[30], v[31]); break;
            default: break;
        }
    } else {
        float4* pp = &g_pooled[g * 8];
        red_add_v4(pp + 0, v[0],  v[1],  v[2],  v[3]);
        red_add_v4(pp + 1, v[4],  v[5],  v[6],  v[7]);
        red_add_v4(pp + 2, v[8],  v[9],  v[10], v[11]);
        red_add_v4(pp + 3, v[12], v[13], v[14], v[15]);
        red_add_v4(pp + 4, v[16], v[17], v[18], v[19]);
        red_add_v4(pp + 5, v[20], v[21], v[22], v[23]);
        red_add_v4(pp + 6, v[24], v[25], v[26], v[27]);
        red_add_v4(pp + 7, v[28], v[29], v[30], v[31]);
    }
}

// ---------------- kernel 3: per-graph head (one warp per graph) -------------
__global__ void __launch_bounds__(32) graph_kernel(
    const float* __restrict__ toz_w, const float* __restrict__ toz_b,
    const float* __restrict__ vp_w1, const float* __restrict__ vp_b1,
    const float* __restrict__ vp_w2, const float* __restrict__ vp_b2,
    const float* __restrict__ bridge_w, const float* __restrict__ bridge_b,
    float* __restrict__ out_recon,   // (1024, 8, 4)
    float* __restrict__ out_z,       // (1024, 2, 4)
    float* __restrict__ out_forces,  // (1024, 2, 2)
    float* __restrict__ out_V)       // (1024, 1)
{
    const unsigned full = 0xffffffffu;
    int g = blockIdx.x;
    int l = threadIdx.x;
    int k = l >> 4;
    int idx = l & 15;

    float p = reinterpret_cast<const float*>(&g_pooled[g * 8])[l];

    float z[8];
#pragma unroll
    for (int c = 0; c < 4; c++) {
        float prod = p * toz_w[idx * 4 + c];
        prod += __shfl_xor_sync(full, prod, 8);
        prod += __shfl_xor_sync(full, prod, 4);
        prod += __shfl_xor_sync(full, prod, 2);
        prod += __shfl_xor_sync(full, prod, 1);
        float zo = prod + toz_b[c];
        float zx = __shfl_xor_sync(full, zo, 16);
        z[k * 4 + c] = zo;
        z[(1 - k) * 4 + c] = zx;
    }

    if (l < 8) out_z[g * 8 + l] = z[l];

    {
        float acc = bridge_b[l];
#pragma unroll
        for (int i = 0; i < 8; i++)
            acc = fmaf(z[i], bridge_w[i * 32 + l], acc);
        out_recon[g * 32 + l] = acc;
    }

    float dx = z[0] - z[4];
    float dy = z[1] - z[5];
    float dist = sqrtf(dx * dx + dy * dy + 1e-6f);

    float w1 = vp_w1[l];
    float w2 = vp_w2[l];
    float tt = fmaf(dist, w1, vp_b1[l]);
    float u  = __expf(-fabsf(tt));
    float sp = fmaxf(tt, 0.f) + __logf(1.f + u);
    float Vp = sp * w2;
    float sig = __frcp_rn(1.f + __expf(-tt));
    float fpp = sig * w1 * w2;

#pragma unroll
    for (int off = 16; off >= 1; off >>= 1) {
        Vp  += __shfl_xor_sync(full, Vp,  off);
        fpp += __shfl_xor_sync(full, fpp, off);
    }

    if (l == 0) {
        float c = fpp / dist;
        out_forces[g * 4 + 0] = -c * dx;
        out_forces[g * 4 + 1] = -c * dy;
        out_forces[g * 4 + 2] =  c * dx;
        out_forces[g * 4 + 3] =  c * dy;
        out_V[g] = Vp + vp_b2[0];
    }
}

// ---------------- launch -----------------------------------------------------
extern "C" void kernel_launch(void* const* d_in, const int* in_sizes, int n_in,
                              void* d_out, int out_size)
{
    const float* x        = (const float*)d_in[0];
    const float* pos      = (const float*)d_in[1];
    const int*   ei       = (const int*)  d_in[2];
    const int*   batch    = (const int*)  d_in[3];
    const float* enc_w1   = (const float*)d_in[4];
    const float* enc_b1   = (const float*)d_in[5];
    const float* enc_w2   = (const float*)d_in[6];
    const float* enc_b2   = (const float*)d_in[7];
    const float* pool_w   = (const float*)d_in[8];
    const float* pool_b   = (const float*)d_in[9];
    const float* toz_w    = (const float*)d_in[10];
    const float* toz_b    = (const float*)d_in[11];
    const float* vp_w1    = (const float*)d_in[12];
    const float* vp_b1    = (const float*)d_in[13];
    const float* vp_w2    = (const float*)d_in[14];
    const float* vp_b2    = (const float*)d_in[15];
    const float* bridge_w = (const float*)d_in[16];
    const float* bridge_b = (const float*)d_in[17];

    float* out = (float*)d_out;
    float* out_recon  = out;                 // 1024*8*4 = 32768
    float* out_z      = out + 32768;         // 1024*2*4 =  8192
    float* out_s      = out + 40960;         // 262144*2 = 524288
    float* out_forces = out + 565248;        // 1024*2*2 =  4096
    float* out_V      = out + 569344;        // 1024

    pre_kernel<<<N_NODES / 256, 256>>>(x, pos);

    // 4 edges per thread
    edge_kernel<<<N_EDGES / 4 / 256, 256>>>(ei, enc_w1, enc_b1);

    node_kernel<<<N_NODES / 256, 256>>>(batch, enc_w2, enc_b2, pool_w, pool_b, out_s);

    graph_kernel<<<NUM_GRAPHS, 32>>>(toz_w, toz_b, vp_w1, vp_b1, vp_w2, vp_b2,
                                     bridge_w, bridge_b,
                                     out_recon, out_z, out_forces, out_V);
}